// round 3
// baseline (speedup 1.0000x reference)
#include <cuda_runtime.h>

#define NN 100000
#define NE 1600000
#define NF 256
#define NH 128
#define NC 8

// Scratch (static __device__ — no runtime allocation allowed)
__device__ __align__(16) float d_g[NN * NC];     // g = X @ Wc, L2-resident (3.2 MB)
__device__ int   d_deg[NN];
__device__ __align__(16) float d_Wc[NF * NC];    // W1 @ Wfc
__device__ __align__(16) float d_bc[NC];         // b1 @ Wfc + bfc

// Detect whether edge_index is int64 (every odd 32-bit word == 0) or int32.
__device__ __forceinline__ bool ei_is64(const int* __restrict__ ei32) {
    return (__ldg(ei32 + 1) == 0) && (__ldg(ei32 + 3) == 0);
}

// ---------------- prologue: fold linear layers + init degrees ----------------
__global__ void k_pre(const float* __restrict__ W1, const float* __restrict__ b1,
                      const float* __restrict__ Wfc, const float* __restrict__ bfc) {
    int idx = blockIdx.x * blockDim.x + threadIdx.x;
    if (idx < NF * NC) {
        int k = idx >> 3, c = idx & 7;
        float s = 0.f;
        #pragma unroll 8
        for (int j = 0; j < NH; j++) s = fmaf(W1[k * NH + j], Wfc[j * NC + c], s);
        d_Wc[idx] = s;
    }
    if (idx < NC) {
        float s = bfc[idx];
        for (int j = 0; j < NH; j++) s = fmaf(b1[j], Wfc[j * NC + idx], s);
        d_bc[idx] = s;
    }
    if (idx < NN) d_deg[idx] = 1;   // self-loop
}

// ---------------- degree histogram: 4 edges / thread ----------------
__global__ void k_deg(const int* __restrict__ ei32) {
    int t = blockIdx.x * blockDim.x + threadIdx.x;     // handles edges 4t..4t+3
    if (4 * t >= NE) return;
    bool is64 = ei_is64(ei32);
    int d0, d1, d2, d3;
    if (is64) {
        const int4* p = (const int4*)(ei32 + 2 * (size_t)NE);  // dst row (int64)
        int4 a = p[t * 2], b = p[t * 2 + 1];
        d0 = a.x; d1 = a.z; d2 = b.x; d3 = b.z;
    } else {
        int4 a = ((const int4*)(ei32 + NE))[t];
        d0 = a.x; d1 = a.y; d2 = a.z; d3 = a.w;
    }
    atomicAdd(&d_deg[d0], 1);
    atomicAdd(&d_deg[d1], 1);
    atomicAdd(&d_deg[d2], 1);
    atomicAdd(&d_deg[d3], 1);
}

// ------- g = X @ Wc (warp per row) + out init (bias + self-loop term) -------
__global__ void k_xw(const float* __restrict__ x, float* __restrict__ out) {
    int lane = threadIdx.x & 31;
    int warp_global = (blockIdx.x * blockDim.x + threadIdx.x) >> 5;
    int nwarps = (gridDim.x * blockDim.x) >> 5;

    // Lane owns features lane*8 .. lane*8+7; its 8x8 slab of Wc in registers.
    float w[8][NC];
    #pragma unroll
    for (int t = 0; t < 8; t++) {
        float4 w0 = ((const float4*)d_Wc)[(lane * 8 + t) * 2];
        float4 w1 = ((const float4*)d_Wc)[(lane * 8 + t) * 2 + 1];
        w[t][0] = w0.x; w[t][1] = w0.y; w[t][2] = w0.z; w[t][3] = w0.w;
        w[t][4] = w1.x; w[t][5] = w1.y; w[t][6] = w1.z; w[t][7] = w1.w;
    }
    bool b16 = lane & 16, b8 = lane & 8, b4 = lane & 4;
    int cidx = (lane >> 2) & 7;          // output column this lane finalizes
    float bcv = d_bc[cidx];

    for (int row = warp_global; row < NN; row += nwarps) {
        const float4* xr = (const float4*)(x + (size_t)row * NF);
        float4 a = xr[lane * 2];
        float4 b = xr[lane * 2 + 1];
        float xs[8] = {a.x, a.y, a.z, a.w, b.x, b.y, b.z, b.w};

        float acc[NC];
        #pragma unroll
        for (int c = 0; c < NC; c++) acc[c] = 0.f;
        #pragma unroll
        for (int t = 0; t < 8; t++)
            #pragma unroll
            for (int c = 0; c < NC; c++) acc[c] = fmaf(xs[t], w[t][c], acc[c]);

        // Value-splitting butterfly: 8 -> 4 -> 2 -> 1 values, then 2 scalar stages.
        float t4[4];
        #pragma unroll
        for (int j = 0; j < 4; j++) {
            float send = b16 ? acc[j] : acc[j + 4];
            float recv = __shfl_xor_sync(0xffffffffu, send, 16);
            t4[j] = (b16 ? acc[j + 4] : acc[j]) + recv;
        }
        float t2[2];
        #pragma unroll
        for (int j = 0; j < 2; j++) {
            float send = b8 ? t4[j] : t4[j + 2];
            float recv = __shfl_xor_sync(0xffffffffu, send, 8);
            t2[j] = (b8 ? t4[j + 2] : t4[j]) + recv;
        }
        float send = b4 ? t2[0] : t2[1];
        float recv = __shfl_xor_sync(0xffffffffu, send, 4);
        float v = (b4 ? t2[1] : t2[0]) + recv;
        v += __shfl_xor_sync(0xffffffffu, v, 2);
        v += __shfl_xor_sync(0xffffffffu, v, 1);

        if ((lane & 3) == 0) {
            // lane 4*c holds column c = (lane>>2)
            d_g[row * NC + cidx] = v;
            float dv = rsqrtf((float)d_deg[row]);
            out[row * NC + cidx] = bcv + dv * dv * v;
        }
    }
}

// ---------------- edge aggregation: 2 edges / thread, v4 RED ----------------
__global__ void k_edges(const int* __restrict__ ei32, float* __restrict__ out) {
    int t = blockIdx.x * blockDim.x + threadIdx.x;     // handles edges 2t, 2t+1
    if (2 * t >= NE) return;
    bool is64 = ei_is64(ei32);
    int s0, s1, d0, d1;
    if (is64) {
        int4 a = ((const int4*)ei32)[t];
        int4 b = ((const int4*)(ei32 + 2 * (size_t)NE))[t];
        s0 = a.x; s1 = a.z; d0 = b.x; d1 = b.z;
    } else {
        int2 a = ((const int2*)ei32)[t];
        int2 b = ((const int2*)(ei32 + NE))[t];
        s0 = a.x; s1 = a.y; d0 = b.x; d1 = b.y;
    }
    float n0 = rsqrtf((float)(d_deg[s0] * d_deg[d0]));
    float n1 = rsqrtf((float)(d_deg[s1] * d_deg[d1]));

    float4 ga0 = ((const float4*)d_g)[s0 * 2];
    float4 ga1 = ((const float4*)d_g)[s0 * 2 + 1];
    float4 gb0 = ((const float4*)d_g)[s1 * 2];
    float4 gb1 = ((const float4*)d_g)[s1 * 2 + 1];

    float4* oa = ((float4*)out) + d0 * 2;
    float4* ob = ((float4*)out) + d1 * 2;
    asm volatile("red.global.add.v4.f32 [%0], {%1, %2, %3, %4};"
                 :: "l"(oa), "f"(ga0.x * n0), "f"(ga0.y * n0), "f"(ga0.z * n0), "f"(ga0.w * n0) : "memory");
    asm volatile("red.global.add.v4.f32 [%0], {%1, %2, %3, %4};"
                 :: "l"(oa + 1), "f"(ga1.x * n0), "f"(ga1.y * n0), "f"(ga1.z * n0), "f"(ga1.w * n0) : "memory");
    asm volatile("red.global.add.v4.f32 [%0], {%1, %2, %3, %4};"
                 :: "l"(ob), "f"(gb0.x * n1), "f"(gb0.y * n1), "f"(gb0.z * n1), "f"(gb0.w * n1) : "memory");
    asm volatile("red.global.add.v4.f32 [%0], {%1, %2, %3, %4};"
                 :: "l"(ob + 1), "f"(gb1.x * n1), "f"(gb1.y * n1), "f"(gb1.z * n1), "f"(gb1.w * n1) : "memory");
}

extern "C" void kernel_launch(void* const* d_in, const int* in_sizes, int n_in,
                              void* d_out, int out_size) {
    const float* x    = (const float*)d_in[0];
    const int*   ei32 = (const int*)d_in[1];   // [2, NE], int32 or int64 (auto-detected)
    const float* W1   = (const float*)d_in[2];
    const float* b1   = (const float*)d_in[3];
    const float* Wfc  = (const float*)d_in[4];
    const float* bfc  = (const float*)d_in[5];
    float* out        = (float*)d_out;

    k_pre<<<(NN + 255) / 256, 256>>>(W1, b1, Wfc, bfc);
    k_deg<<<(NE / 4 + 255) / 256, 256>>>(ei32);
    k_xw<<<1184, 256>>>(x, out);
    k_edges<<<(NE / 2 + 255) / 256, 256>>>(ei32, out);
}